// round 3
// baseline (speedup 1.0000x reference)
#include <cuda_runtime.h>

#define LMAX 32768
#define NMAX 32768
#define TCB 256    // backward: candidate tile per block (smem, duplicated-packed)
#define TTF 256    // forward: target tile per block (smem, duplicated-packed)
#define CHK 32     // chunk size for index rescan

#define POSINF __int_as_float(0x7F800000)
#define NEGINF __int_as_float(0xFF800000)

typedef unsigned long long ull;

// ---------------- device scratch (no allocations allowed) ----------------
__device__ unsigned int  g_keys[LMAX];
__device__ unsigned char g_islm[LMAX];
__device__ float         g_thr;
__device__ int           g_count;
__device__ int           g_ecount;
__device__ float4        g_candC2[2 * LMAX];  // per kept cand: (x,x,y,y) and (z,z,-h,-h)
__device__ int           g_candIdx[LMAX];     // compacted kept -> original index
__device__ ull           g_bwd[NMAX];         // per target: (sortable(-smax)<<32)|candOrigIdx
__device__ ull           g_fwd[LMAX];         // per cand:   (sortable(-smax)<<32)|tgtIdx
__device__ float         g_num[LMAX * 3];
__device__ float         g_den[LMAX];
__device__ int           g_exact[LMAX];
__device__ float         g_exrgb[LMAX * 3];
__device__ float4        g_eC[LMAX];          // compacted empty cands: x,y,z, bits(origIdx)

// ---------------- helpers ----------------
__device__ __forceinline__ unsigned f2u(float f) {
    unsigned i = __float_as_uint(f);
    return (i & 0x80000000u) ? ~i : (i | 0x80000000u);
}
__device__ __forceinline__ float u2f(unsigned u) {
    unsigned i = (u & 0x80000000u) ? (u & 0x7FFFFFFFu) : ~u;
    return __uint_as_float(i);
}
__device__ __forceinline__ ull fma2(ull a, ull b, ull c) {
    ull d;
    asm("fma.rn.f32x2 %0, %1, %2, %3;" : "=l"(d) : "l"(a), "l"(b), "l"(c));
    return d;
}
__device__ __forceinline__ ull pk2(float lo, float hi) {
    ull r;
    asm("mov.b64 %0, {%1, %2};" : "=l"(r) : "f"(lo), "f"(hi));
    return r;
}
__device__ __forceinline__ void up2(ull v, float& lo, float& hi) {
    asm("mov.b64 {%0, %1}, %2;" : "=f"(lo), "=f"(hi) : "l"(v));
}

__device__ __forceinline__ float blockReduceSum(float v) {
    __shared__ float sh[32];
    int lane = threadIdx.x & 31, w = threadIdx.x >> 5;
#pragma unroll
    for (int o = 16; o > 0; o >>= 1) v += __shfl_down_sync(0xFFFFFFFFu, v, o);
    if (lane == 0) sh[w] = v;
    __syncthreads();
    v = (threadIdx.x < (blockDim.x >> 5)) ? sh[lane] : 0.f;
    if (w == 0) {
#pragma unroll
        for (int o = 16; o > 0; o >>= 1) v += __shfl_down_sync(0xFFFFFFFFu, v, o);
    }
    return v;
}

// ---------------- kernels ----------------
// init of all scratch + local-max over groups of 8 + sortable keys (fused)
__global__ void k_initprep(const float* __restrict__ pred, float* out, int L, int N) {
    int i = blockIdx.x * blockDim.x + threadIdx.x;
    if (i == 0) { g_count = 0; g_ecount = 0; out[0] = 0.f; out[1] = 0.f; }
    if (i < L) {
        g_num[3 * i] = 0.f; g_num[3 * i + 1] = 0.f; g_num[3 * i + 2] = 0.f;
        g_den[i] = 0.f; g_exact[i] = 0;
        g_fwd[i] = 0xFFFFFFFFFFFFFFFFULL;
    }
    if (i < N) g_bwd[i] = 0xFFFFFFFFFFFFFFFFULL;
    int G = L >> 3;
    if (i < G) {
        const float* p = pred + i * 8;
        float bv = p[0]; int bi = 0;
#pragma unroll
        for (int j = 1; j < 8; j++) { float v = p[j]; if (v > bv) { bv = v; bi = j; } }
#pragma unroll
        for (int j = 0; j < 8; j++) {
            bool lm = (j == bi);
            g_islm[i * 8 + j] = lm ? 1 : 0;
            g_keys[i * 8 + j] = f2u(lm ? POSINF : p[j]);
        }
    }
}

// single-block MSD radix select: threshold = k-th smallest of keys, k = L - points_num
__global__ void k_select(const int* __restrict__ pn, int L) {
    __shared__ unsigned hist[256];
    __shared__ unsigned s_prefix;
    __shared__ int s_rank;
    int tid = threadIdx.x;
    if (tid == 0) { s_prefix = 0u; s_rank = L - pn[0]; }
    __syncthreads();
    for (int round = 0; round < 4; round++) {
        int shift = 24 - 8 * round;
        hist[tid] = 0u;
        __syncthreads();
        unsigned pref = s_prefix;
        unsigned mask = (round == 0) ? 0u : (0xFFFFFFFFu << (shift + 8));
        for (int i = tid; i < L; i += 256) {
            unsigned u = g_keys[i];
            if ((u & mask) == pref) atomicAdd(&hist[(u >> shift) & 0xFFu], 1u);
        }
        __syncthreads();
        if (tid == 0) {
            int r = s_rank; unsigned b = 0;
            while (b < 256u) { int c = (int)hist[b]; if (c >= r) break; r -= c; b++; }
            s_rank = r;
            s_prefix = pref | (b << shift);
        }
        __syncthreads();
    }
    if (tid == 0) g_thr = u2f(s_prefix);
}

// keep mask, BCE (coord loss), warp-aggregated compaction (duplicated-packed layout)
__global__ void k_keep(const float* __restrict__ pred, const int* __restrict__ kt,
                       const float* __restrict__ cxyz, int L, float* out) {
    int i = blockIdx.x * blockDim.x + threadIdx.x;
    float bce = 0.f; bool keep = false;
    float thr = g_thr;
    if (i < L) {
        float p = pred[i];
        float t = (float)kt[i];
        bce = fmaxf(p, 0.f) - p * t + log1pf(expf(-fabsf(p)));
        keep = (p > thr) || (g_islm[i] != 0);
    }
    unsigned m = __ballot_sync(0xFFFFFFFFu, keep);
    if (keep) {
        int lane = threadIdx.x & 31;
        int leader = __ffs(m) - 1;
        int base = 0;
        if (lane == leader) base = atomicAdd(&g_count, __popc(m));
        base = __shfl_sync(m, base, leader);
        int pos = base + __popc(m & ((1u << lane) - 1u));
        float x = cxyz[3 * i], y = cxyz[3 * i + 1], z = cxyz[3 * i + 2];
        float mh = -0.5f * fmaf(z, z, fmaf(y, y, x * x));
        g_candC2[2 * pos]     = make_float4(x, x, y, y);
        g_candC2[2 * pos + 1] = make_float4(z, z, mh, mh);
        g_candIdx[pos] = i;
    }
    float s = blockReduceSum(bce);
    if (threadIdx.x == 0) atomicAdd(out, s);
}

// backward sweep: per target, argmax of s = dot(t,c) - 0.5|c|^2 over kept candidates.
// 4 targets/thread, packed f32x2 math, chunked max + exact rescan for the index.
__global__ void k_bwd(const float* __restrict__ txyz, int N) {
    __shared__ float4 sA[TCB], sB[TCB];
    int count = g_count;
    int tstart = blockIdx.x * TCB;
    if (tstart >= count) return;
    int tid = threadIdx.x;
    for (int j = tid; j < TCB; j += blockDim.x) {
        int p = tstart + j;
        if (p < count) { sA[j] = g_candC2[2 * p]; sB[j] = g_candC2[2 * p + 1]; }
        else { sA[j] = make_float4(0.f, 0.f, 0.f, 0.f); sB[j] = make_float4(0.f, 0.f, NEGINF, NEGINF); }
    }
    __syncthreads();

    int t0 = blockIdx.y * 1024 + tid;
    int t1 = t0 + 256, t2 = t0 + 512, t3 = t0 + 768;
    bool v0 = t0 < N, v1 = t1 < N, v2 = t2 < N, v3 = t3 < N;
    float x0 = v0 ? txyz[3 * t0] : 0.f, y0 = v0 ? txyz[3 * t0 + 1] : 0.f, z0 = v0 ? txyz[3 * t0 + 2] : 0.f;
    float x1 = v1 ? txyz[3 * t1] : 0.f, y1 = v1 ? txyz[3 * t1 + 1] : 0.f, z1 = v1 ? txyz[3 * t1 + 2] : 0.f;
    float x2 = v2 ? txyz[3 * t2] : 0.f, y2 = v2 ? txyz[3 * t2 + 1] : 0.f, z2 = v2 ? txyz[3 * t2 + 2] : 0.f;
    float x3 = v3 ? txyz[3 * t3] : 0.f, y3 = v3 ? txyz[3 * t3 + 1] : 0.f, z3 = v3 ? txyz[3 * t3 + 2] : 0.f;
    ull tx01 = pk2(x0, x1), ty01 = pk2(y0, y1), tz01 = pk2(z0, z1);
    ull tx23 = pk2(x2, x3), ty23 = pk2(y2, y3), tz23 = pk2(z2, z3);

    float b0 = NEGINF, b1 = NEGINF, b2 = NEGINF, b3 = NEGINF;
    int k0 = 0, k1 = 0, k2 = 0, k3 = 0;
    for (int cs = 0; cs < TCB; cs += CHK) {
        float c0 = NEGINF, c1 = NEGINF, c2 = NEGINF, c3 = NEGINF;
#pragma unroll 16
        for (int j = cs; j < cs + CHK; j++) {
            ulonglong2 qa = *reinterpret_cast<const ulonglong2*>(&sA[j]);
            ulonglong2 qb = *reinterpret_cast<const ulonglong2*>(&sB[j]);
            ull s01 = fma2(qa.x, tx01, fma2(qa.y, ty01, fma2(qb.x, tz01, qb.y)));
            ull s23 = fma2(qa.x, tx23, fma2(qa.y, ty23, fma2(qb.x, tz23, qb.y)));
            float s0, s1, s2, s3;
            up2(s01, s0, s1); up2(s23, s2, s3);
            c0 = fmaxf(c0, s0); c1 = fmaxf(c1, s1);
            c2 = fmaxf(c2, s2); c3 = fmaxf(c3, s3);
        }
        if (c0 > b0) { b0 = c0; k0 = cs; }
        if (c1 > b1) { b1 = c1; k1 = cs; }
        if (c2 > b2) { b2 = c2; k2 = cs; }
        if (c3 > b3) { b3 = c3; k3 = cs; }
    }

#define BWD_RESCAN(V, T, B, KC, TX, TY, TZ)                                          \
    if (V) {                                                                         \
        int bj = -1;                                                                 \
        for (int j = KC; j < KC + CHK; j++) {                                        \
            float s = fmaf(sA[j].x, TX, fmaf(sA[j].z, TY, fmaf(sB[j].x, TZ, sB[j].z))); \
            if (s == B) { bj = j; break; }                                           \
        }                                                                            \
        if (bj >= 0) {                                                               \
            ull pk = ((ull)f2u(-(B)) << 32) | (unsigned)g_candIdx[tstart + bj];      \
            atomicMin(&g_bwd[T], pk);                                                \
        }                                                                            \
    }
    BWD_RESCAN(v0, t0, b0, k0, x0, y0, z0)
    BWD_RESCAN(v1, t1, b1, k1, x1, y1, z1)
    BWD_RESCAN(v2, t2, b2, k2, x2, y2, z2)
    BWD_RESCAN(v3, t3, b3, k3, x3, y3, z3)
#undef BWD_RESCAN
}

// per target: scatter weighted rgb into the winning candidate
__global__ void k_scatter(const float* __restrict__ txyz, const float* __restrict__ trgb, int N) {
    int n = blockIdx.x * blockDim.x + threadIdx.x;
    if (n >= N) return;
    ull pk = g_bwd[n];
    if (pk == 0xFFFFFFFFFFFFFFFFULL) return;
    unsigned u = (unsigned)(pk >> 32);
    int idx = (int)(unsigned)(pk & 0xFFFFFFFFULL);
    float m = u2f(u);  // m = h - dot, d2 = t2 + 2m
    float tx = txyz[3 * n], ty = txyz[3 * n + 1], tz = txyz[3 * n + 2];
    float t2 = fmaf(tz, tz, fmaf(ty, ty, tx * tx));
    float d2 = fmaxf(fmaf(2.f, m, t2), 0.f);
    float r = trgb[3 * n], g = trgb[3 * n + 1], b = trgb[3 * n + 2];
    if (d2 == 0.f) {
        g_exact[idx] = 1;
        g_exrgb[3 * idx] = r; g_exrgb[3 * idx + 1] = g; g_exrgb[3 * idx + 2] = b;
    } else {
        float w = 1.0f / sqrtf(fmaxf(d2, 1e-30f));
        atomicAdd(&g_num[3 * idx],     r * w);
        atomicAdd(&g_num[3 * idx + 1], g * w);
        atomicAdd(&g_num[3 * idx + 2], b * w);
        atomicAdd(&g_den[idx], w);
    }
}

// compact kept candidates that received no color (the "empty" set)
__global__ void k_compactE(int L) {
    int p = blockIdx.x * blockDim.x + threadIdx.x;
    bool e = false; int l = 0;
    float x = 0.f, y = 0.f, z = 0.f;
    if (p < g_count) {
        l = g_candIdx[p];
        if (g_den[l] == 0.f && g_exact[l] == 0) {
            e = true;
            float4 a = g_candC2[2 * p];
            float4 b = g_candC2[2 * p + 1];
            x = a.x; y = a.z; z = b.x;
        }
    }
    unsigned m = __ballot_sync(0xFFFFFFFFu, e);
    if (e) {
        int lane = threadIdx.x & 31;
        int leader = __ffs(m) - 1;
        int base = 0;
        if (lane == leader) base = atomicAdd(&g_ecount, __popc(m));
        base = __shfl_sync(m, base, leader);
        int pos = base + __popc(m & ((1u << lane) - 1u));
        g_eC[pos] = make_float4(x, y, z, __int_as_float(l));
    }
}

// forward sweep: per empty candidate, argmax of s = dot(c,t) - 0.5|t|^2 over all targets.
// 2 candidates/thread, packed f32x2, chunked max + exact rescan.
__global__ void k_fwd(const float* __restrict__ txyz, int N) {
    int ec = g_ecount;
    int estart = blockIdx.x * 512;
    if (estart >= ec) return;
    __shared__ float4 sA[TTF], sB[TTF];
    int tid = threadIdx.x;
    int tstart = blockIdx.y * TTF;
    for (int j = tid; j < TTF; j += blockDim.x) {
        int t = tstart + j;
        if (t < N) {
            float x = txyz[3 * t], y = txyz[3 * t + 1], z = txyz[3 * t + 2];
            float mh = -0.5f * fmaf(z, z, fmaf(y, y, x * x));
            sA[j] = make_float4(x, x, y, y);
            sB[j] = make_float4(z, z, mh, mh);
        } else {
            sA[j] = make_float4(0.f, 0.f, 0.f, 0.f);
            sB[j] = make_float4(0.f, 0.f, NEGINF, NEGINF);
        }
    }
    __syncthreads();

    int e0 = estart + tid, e1 = e0 + 256;
    bool v0 = e0 < ec, v1 = e1 < ec;
    float4 c0 = v0 ? g_eC[e0] : make_float4(0.f, 0.f, 0.f, 0.f);
    float4 c1 = v1 ? g_eC[e1] : make_float4(0.f, 0.f, 0.f, 0.f);
    ull cx01 = pk2(c0.x, c1.x), cy01 = pk2(c0.y, c1.y), cz01 = pk2(c0.z, c1.z);

    float b0 = NEGINF, b1 = NEGINF;
    int k0 = 0, k1 = 0;
    for (int cs = 0; cs < TTF; cs += CHK) {
        float m0 = NEGINF, m1 = NEGINF;
#pragma unroll 16
        for (int j = cs; j < cs + CHK; j++) {
            ulonglong2 qa = *reinterpret_cast<const ulonglong2*>(&sA[j]);
            ulonglong2 qb = *reinterpret_cast<const ulonglong2*>(&sB[j]);
            ull s01 = fma2(qa.x, cx01, fma2(qa.y, cy01, fma2(qb.x, cz01, qb.y)));
            float s0, s1;
            up2(s01, s0, s1);
            m0 = fmaxf(m0, s0); m1 = fmaxf(m1, s1);
        }
        if (m0 > b0) { b0 = m0; k0 = cs; }
        if (m1 > b1) { b1 = m1; k1 = cs; }
    }

#define FWD_RESCAN(V, C, B, KC)                                                        \
    if (V) {                                                                           \
        int bj = -1;                                                                   \
        for (int j = KC; j < KC + CHK; j++) {                                          \
            float s = fmaf(sA[j].x, (C).x, fmaf(sA[j].z, (C).y, fmaf(sB[j].x, (C).z, sB[j].z))); \
            if (s == B) { bj = j; break; }                                             \
        }                                                                              \
        if (bj >= 0) {                                                                 \
            int l = __float_as_int((C).w);                                             \
            ull pk = ((ull)f2u(-(B)) << 32) | (unsigned)(tstart + bj);                 \
            atomicMin(&g_fwd[l], pk);                                                  \
        }                                                                              \
    }
    FWD_RESCAN(v0, c0, b0, k0)
    FWD_RESCAN(v1, c1, b1, k1)
#undef FWD_RESCAN
}

// final L1 loss over kept candidates
__global__ void k_final(const float* __restrict__ crgb, const float* __restrict__ trgb,
                        float* out, int N) {
    int p = blockIdx.x * blockDim.x + threadIdx.x;
    float loss = 0.f;
    if (p < g_count) {
        int l = g_candIdx[p];
        float r0, r1, r2;
        if (g_exact[l]) {
            r0 = g_exrgb[3 * l]; r1 = g_exrgb[3 * l + 1]; r2 = g_exrgb[3 * l + 2];
        } else {
            float den = g_den[l];
            if (den != 0.f) {
                r0 = g_num[3 * l] / den;
                r1 = g_num[3 * l + 1] / den;
                r2 = g_num[3 * l + 2] / den;
            } else {
                ull pk = g_fwd[l];
                unsigned ti = (unsigned)(pk & 0xFFFFFFFFULL);
                if (ti < (unsigned)N) {
                    r0 = trgb[3 * ti]; r1 = trgb[3 * ti + 1]; r2 = trgb[3 * ti + 2];
                } else {
                    r0 = r1 = r2 = 0.f;
                }
            }
        }
        float q0 = crgb[3 * l] * 255.f;
        float q1 = crgb[3 * l + 1] * 255.f;
        float q2 = crgb[3 * l + 2] * 255.f;
        loss = fabsf(q0 - r0) + fabsf(q1 - r1) + fabsf(q2 - r2);
    }
    float s = blockReduceSum(loss);
    if (threadIdx.x == 0) atomicAdd(out + 1, s);
}

// ---------------- launch ----------------
extern "C" void kernel_launch(void* const* d_in, const int* in_sizes, int n_in,
                              void* d_out, int out_size) {
    const float* pred = (const float*)d_in[0];
    const float* cxyz = (const float*)d_in[1];
    const float* crgb = (const float*)d_in[2];
    const float* txyz = (const float*)d_in[3];
    const float* trgb = (const float*)d_in[4];
    const int*   kt   = (const int*)d_in[5];
    const int*   pn   = (const int*)d_in[6];
    float* out = (float*)d_out;

    int L = in_sizes[0];
    int N = in_sizes[3] / 3;
    int M = L > N ? L : N;

    k_initprep<<<(M + 255) / 256, 256>>>(pred, out, L, N);
    k_select<<<1, 256>>>(pn, L);
    k_keep<<<(L + 255) / 256, 256>>>(pred, kt, cxyz, L, out);
    dim3 gb((L + TCB - 1) / TCB, (N + 1023) / 1024);
    k_bwd<<<gb, 256>>>(txyz, N);
    k_scatter<<<(N + 255) / 256, 256>>>(txyz, trgb, N);
    k_compactE<<<(L + 255) / 256, 256>>>(L);
    dim3 gf((L + 511) / 512, (N + TTF - 1) / TTF);
    k_fwd<<<gf, 256>>>(txyz, N);
    k_final<<<(L + 255) / 256, 256>>>(crgb, trgb, out, N);
}

// round 4
// speedup vs baseline: 1.3445x; 1.3445x over previous
#include <cuda_runtime.h>

#define LMAX 32768
#define NMAX 32768
#define TCB 1024   // backward: candidates per smem tile (pairwise-packed, 16KB)
#define TTF 1024   // forward: targets per smem tile (pairwise-packed, 16KB)
#define CHKP 32    // chunk in candidate-PAIRS (64 candidates) for index rescan

#define POSINF __int_as_float(0x7F800000)
#define NEGINF __int_as_float(0xFF800000)

typedef unsigned long long ull;

// ---------------- device scratch (no allocations allowed) ----------------
__device__ unsigned int  g_keys[LMAX];
__device__ unsigned char g_islm[LMAX];
__device__ float         g_thr;
__device__ int           g_count;
__device__ int           g_ecount;
__device__ float4        g_candC[LMAX];     // kept cand: x,y,z, mh=-0.5*|c|^2
__device__ int           g_candIdx[LMAX];   // compacted kept -> original index
__device__ ull           g_bwd[NMAX];       // per target: (sortable(-smax)<<32)|candOrigIdx
__device__ ull           g_fwd[LMAX];       // per cand:   (sortable(-smax)<<32)|tgtIdx
__device__ float         g_num[LMAX * 3];
__device__ float         g_den[LMAX];
__device__ int           g_exact[LMAX];
__device__ float         g_exrgb[LMAX * 3];
__device__ float4        g_eC[LMAX];        // compacted empty cands: x,y,z, bits(origIdx)

// ---------------- helpers ----------------
__device__ __forceinline__ unsigned f2u(float f) {
    unsigned i = __float_as_uint(f);
    return (i & 0x80000000u) ? ~i : (i | 0x80000000u);
}
__device__ __forceinline__ float u2f(unsigned u) {
    unsigned i = (u & 0x80000000u) ? (u & 0x7FFFFFFFu) : ~u;
    return __uint_as_float(i);
}
__device__ __forceinline__ ull fma2(ull a, ull b, ull c) {
    ull d;
    asm("fma.rn.f32x2 %0, %1, %2, %3;" : "=l"(d) : "l"(a), "l"(b), "l"(c));
    return d;
}
__device__ __forceinline__ ull pk2(float lo, float hi) {
    ull r;
    asm("mov.b64 %0, {%1, %2};" : "=l"(r) : "f"(lo), "f"(hi));
    return r;
}
__device__ __forceinline__ void up2(ull v, float& lo, float& hi) {
    asm("mov.b64 {%0, %1}, %2;" : "=f"(lo), "=f"(hi) : "l"(v));
}

__device__ __forceinline__ float blockReduceSum(float v) {
    __shared__ float sh[32];
    int lane = threadIdx.x & 31, w = threadIdx.x >> 5;
#pragma unroll
    for (int o = 16; o > 0; o >>= 1) v += __shfl_down_sync(0xFFFFFFFFu, v, o);
    if (lane == 0) sh[w] = v;
    __syncthreads();
    v = (threadIdx.x < (blockDim.x >> 5)) ? sh[lane] : 0.f;
    if (w == 0) {
#pragma unroll
        for (int o = 16; o > 0; o >>= 1) v += __shfl_down_sync(0xFFFFFFFFu, v, o);
    }
    return v;
}

// ---------------- kernels ----------------
// init of all scratch + local-max over groups of 8 + sortable keys (fused)
__global__ void k_initprep(const float* __restrict__ pred, float* out, int L, int N) {
    int i = blockIdx.x * blockDim.x + threadIdx.x;
    if (i == 0) { g_count = 0; g_ecount = 0; out[0] = 0.f; out[1] = 0.f; }
    if (i < L) {
        g_num[3 * i] = 0.f; g_num[3 * i + 1] = 0.f; g_num[3 * i + 2] = 0.f;
        g_den[i] = 0.f; g_exact[i] = 0;
        g_fwd[i] = 0xFFFFFFFFFFFFFFFFULL;
    }
    if (i < N) g_bwd[i] = 0xFFFFFFFFFFFFFFFFULL;
    int G = L >> 3;
    if (i < G) {
        const float* p = pred + i * 8;
        float bv = p[0]; int bi = 0;
#pragma unroll
        for (int j = 1; j < 8; j++) { float v = p[j]; if (v > bv) { bv = v; bi = j; } }
#pragma unroll
        for (int j = 0; j < 8; j++) {
            bool lm = (j == bi);
            g_islm[i * 8 + j] = lm ? 1 : 0;
            g_keys[i * 8 + j] = f2u(lm ? POSINF : p[j]);
        }
    }
}

// single-block MSD radix select: threshold = k-th smallest of keys, k = L - points_num
__global__ void k_select(const int* __restrict__ pn, int L) {
    __shared__ unsigned hist[256];
    __shared__ unsigned s_prefix;
    __shared__ int s_rank;
    int tid = threadIdx.x;
    if (tid == 0) { s_prefix = 0u; s_rank = L - pn[0]; }
    __syncthreads();
    for (int round = 0; round < 4; round++) {
        int shift = 24 - 8 * round;
        hist[tid] = 0u;
        __syncthreads();
        unsigned pref = s_prefix;
        unsigned mask = (round == 0) ? 0u : (0xFFFFFFFFu << (shift + 8));
        for (int i = tid; i < L; i += 256) {
            unsigned u = g_keys[i];
            if ((u & mask) == pref) atomicAdd(&hist[(u >> shift) & 0xFFu], 1u);
        }
        __syncthreads();
        if (tid == 0) {
            int r = s_rank; unsigned b = 0;
            while (b < 256u) { int c = (int)hist[b]; if (c >= r) break; r -= c; b++; }
            s_rank = r;
            s_prefix = pref | (b << shift);
        }
        __syncthreads();
    }
    if (tid == 0) g_thr = u2f(s_prefix);
}

// keep mask, BCE (coord loss), warp-aggregated compaction
__global__ void k_keep(const float* __restrict__ pred, const int* __restrict__ kt,
                       const float* __restrict__ cxyz, int L, float* out) {
    int i = blockIdx.x * blockDim.x + threadIdx.x;
    float bce = 0.f; bool keep = false;
    float thr = g_thr;
    if (i < L) {
        float p = pred[i];
        float t = (float)kt[i];
        bce = fmaxf(p, 0.f) - p * t + log1pf(expf(-fabsf(p)));
        keep = (p > thr) || (g_islm[i] != 0);
    }
    unsigned m = __ballot_sync(0xFFFFFFFFu, keep);
    if (keep) {
        int lane = threadIdx.x & 31;
        int leader = __ffs(m) - 1;
        int base = 0;
        if (lane == leader) base = atomicAdd(&g_count, __popc(m));
        base = __shfl_sync(m, base, leader);
        int pos = base + __popc(m & ((1u << lane) - 1u));
        float x = cxyz[3 * i], y = cxyz[3 * i + 1], z = cxyz[3 * i + 2];
        float mh = -0.5f * fmaf(z, z, fmaf(y, y, x * x));
        g_candC[pos] = make_float4(x, y, z, mh);
        g_candIdx[pos] = i;
    }
    float s = blockReduceSum(bce);
    if (threadIdx.x == 0) atomicAdd(out, s);
}

// backward sweep: per target, argmax of s = dot(t,c) - 0.5|c|^2 over kept candidates.
// Candidates pairwise-packed into f32x2 lanes; 2 targets/thread; chunk max + exact rescan.
// smem: sP[jp]=(x_even,x_odd,y_even,y_odd), sQ[jp]=(z_even,z_odd,mh_even,mh_odd)
__global__ void __launch_bounds__(256) k_bwd(const float* __restrict__ txyz, int N) {
    __shared__ float4 sP[TCB / 2], sQ[TCB / 2];
    int count = g_count;
    int tstart = blockIdx.x * TCB;
    if (tstart >= count) return;
    int tid = threadIdx.x;
    for (int j = tid; j < TCB; j += 256) {
        int p = tstart + j;
        float4 c = (p < count) ? g_candC[p] : make_float4(0.f, 0.f, 0.f, NEGINF);
        int jp = j >> 1;
        if ((j & 1) == 0) { sP[jp].x = c.x; sP[jp].z = c.y; sQ[jp].x = c.z; sQ[jp].z = c.w; }
        else              { sP[jp].y = c.x; sP[jp].w = c.y; sQ[jp].y = c.z; sQ[jp].w = c.w; }
    }
    __syncthreads();

    int tA = blockIdx.y * 512 + tid;
    int tB = tA + 256;
    bool vA = tA < N, vB = tB < N;
    float xA = vA ? txyz[3 * tA] : 0.f, yA = vA ? txyz[3 * tA + 1] : 0.f, zA = vA ? txyz[3 * tA + 2] : 0.f;
    float xB = vB ? txyz[3 * tB] : 0.f, yB = vB ? txyz[3 * tB + 1] : 0.f, zB = vB ? txyz[3 * tB + 2] : 0.f;
    ull txA = pk2(xA, xA), tyA = pk2(yA, yA), tzA = pk2(zA, zA);
    ull txB = pk2(xB, xB), tyB = pk2(yB, yB), tzB = pk2(zB, zB);

    float bestA = NEGINF, bestB = NEGINF;
    int kA = 0, kB = 0;
    for (int cs = 0; cs < TCB / 2; cs += CHKP) {
        float a0 = NEGINF, a1 = NEGINF, c0 = NEGINF, c1 = NEGINF;
#pragma unroll 8
        for (int jp = cs; jp < cs + CHKP; jp++) {
            ulonglong2 qp = *reinterpret_cast<const ulonglong2*>(&sP[jp]);
            ulonglong2 qq = *reinterpret_cast<const ulonglong2*>(&sQ[jp]);
            ull sA = fma2(qp.x, txA, fma2(qp.y, tyA, fma2(qq.x, tzA, qq.y)));
            ull sB = fma2(qp.x, txB, fma2(qp.y, tyB, fma2(qq.x, tzB, qq.y)));
            float lA, hA, lB, hB;
            up2(sA, lA, hA); up2(sB, lB, hB);
            a0 = fmaxf(a0, lA); a1 = fmaxf(a1, hA);
            c0 = fmaxf(c0, lB); c1 = fmaxf(c1, hB);
        }
        float mA = fmaxf(a0, a1), mB = fmaxf(c0, c1);
        if (mA > bestA) { bestA = mA; kA = cs; }
        if (mB > bestB) { bestB = mB; kB = cs; }
    }

#define BWD_RESCAN(V, T, BV, KC, TX, TY, TZ)                                               \
    if (V) {                                                                               \
        int bidx = -1;                                                                     \
        for (int jp = KC; jp < KC + CHKP; jp++) {                                          \
            float s0 = fmaf(sP[jp].x, TX, fmaf(sP[jp].z, TY, fmaf(sQ[jp].x, TZ, sQ[jp].z))); \
            if (s0 == BV) { bidx = 2 * jp; break; }                                        \
            float s1 = fmaf(sP[jp].y, TX, fmaf(sP[jp].w, TY, fmaf(sQ[jp].y, TZ, sQ[jp].w))); \
            if (s1 == BV) { bidx = 2 * jp + 1; break; }                                    \
        }                                                                                  \
        if (bidx >= 0) {                                                                   \
            ull pk = ((ull)f2u(-(BV)) << 32) | (unsigned)g_candIdx[tstart + bidx];         \
            atomicMin(&g_bwd[T], pk);                                                      \
        }                                                                                  \
    }
    BWD_RESCAN(vA, tA, bestA, kA, xA, yA, zA)
    BWD_RESCAN(vB, tB, bestB, kB, xB, yB, zB)
#undef BWD_RESCAN
}

// per target: scatter weighted rgb into the winning candidate
__global__ void k_scatter(const float* __restrict__ txyz, const float* __restrict__ trgb, int N) {
    int n = blockIdx.x * blockDim.x + threadIdx.x;
    if (n >= N) return;
    ull pk = g_bwd[n];
    if (pk == 0xFFFFFFFFFFFFFFFFULL) return;
    unsigned u = (unsigned)(pk >> 32);
    int idx = (int)(unsigned)(pk & 0xFFFFFFFFULL);
    float m = u2f(u);  // m = h - dot, d2 = t2 + 2m
    float tx = txyz[3 * n], ty = txyz[3 * n + 1], tz = txyz[3 * n + 2];
    float t2 = fmaf(tz, tz, fmaf(ty, ty, tx * tx));
    float d2 = fmaxf(fmaf(2.f, m, t2), 0.f);
    float r = trgb[3 * n], g = trgb[3 * n + 1], b = trgb[3 * n + 2];
    if (d2 == 0.f) {
        g_exact[idx] = 1;
        g_exrgb[3 * idx] = r; g_exrgb[3 * idx + 1] = g; g_exrgb[3 * idx + 2] = b;
    } else {
        float w = 1.0f / sqrtf(fmaxf(d2, 1e-30f));
        atomicAdd(&g_num[3 * idx],     r * w);
        atomicAdd(&g_num[3 * idx + 1], g * w);
        atomicAdd(&g_num[3 * idx + 2], b * w);
        atomicAdd(&g_den[idx], w);
    }
}

// compact kept candidates that received no color (the "empty" set)
__global__ void k_compactE(int L) {
    int p = blockIdx.x * blockDim.x + threadIdx.x;
    bool e = false; int l = 0;
    float x = 0.f, y = 0.f, z = 0.f;
    if (p < g_count) {
        l = g_candIdx[p];
        if (g_den[l] == 0.f && g_exact[l] == 0) {
            e = true;
            float4 c = g_candC[p];
            x = c.x; y = c.y; z = c.z;
        }
    }
    unsigned m = __ballot_sync(0xFFFFFFFFu, e);
    if (e) {
        int lane = threadIdx.x & 31;
        int leader = __ffs(m) - 1;
        int base = 0;
        if (lane == leader) base = atomicAdd(&g_ecount, __popc(m));
        base = __shfl_sync(m, base, leader);
        int pos = base + __popc(m & ((1u << lane) - 1u));
        g_eC[pos] = make_float4(x, y, z, __int_as_float(l));
    }
}

// forward sweep: per empty candidate, argmax of s = dot(c,t) - 0.5|t|^2 over all targets.
// Targets pairwise-packed into f32x2 lanes; 1 empty cand/thread; chunk max + exact rescan.
__global__ void __launch_bounds__(256) k_fwd(const float* __restrict__ txyz, int N) {
    int ec = g_ecount;
    int estart = blockIdx.x * 256;
    if (estart >= ec) return;
    __shared__ float4 sP[TTF / 2], sQ[TTF / 2];
    int tid = threadIdx.x;
    int tstart = blockIdx.y * TTF;
    for (int j = tid; j < TTF; j += 256) {
        int t = tstart + j;
        float x = 0.f, y = 0.f, z = 0.f, mh = NEGINF;
        if (t < N) {
            x = txyz[3 * t]; y = txyz[3 * t + 1]; z = txyz[3 * t + 2];
            mh = -0.5f * fmaf(z, z, fmaf(y, y, x * x));
        }
        int jp = j >> 1;
        if ((j & 1) == 0) { sP[jp].x = x; sP[jp].z = y; sQ[jp].x = z; sQ[jp].z = mh; }
        else              { sP[jp].y = x; sP[jp].w = y; sQ[jp].y = z; sQ[jp].w = mh; }
    }
    __syncthreads();

    int e = estart + tid;
    bool v = e < ec;
    float4 c = v ? g_eC[e] : make_float4(0.f, 0.f, 0.f, 0.f);
    ull cx = pk2(c.x, c.x), cy = pk2(c.y, c.y), cz = pk2(c.z, c.z);

    float best = NEGINF; int kc = 0;
    for (int cs = 0; cs < TTF / 2; cs += CHKP) {
        float a0 = NEGINF, a1 = NEGINF;
#pragma unroll 8
        for (int jp = cs; jp < cs + CHKP; jp++) {
            ulonglong2 qp = *reinterpret_cast<const ulonglong2*>(&sP[jp]);
            ulonglong2 qq = *reinterpret_cast<const ulonglong2*>(&sQ[jp]);
            ull s = fma2(qp.x, cx, fma2(qp.y, cy, fma2(qq.x, cz, qq.y)));
            float lo, hi;
            up2(s, lo, hi);
            a0 = fmaxf(a0, lo); a1 = fmaxf(a1, hi);
        }
        float m = fmaxf(a0, a1);
        if (m > best) { best = m; kc = cs; }
    }

    if (v) {
        int bidx = -1;
        for (int jp = kc; jp < kc + CHKP; jp++) {
            float s0 = fmaf(sP[jp].x, c.x, fmaf(sP[jp].z, c.y, fmaf(sQ[jp].x, c.z, sQ[jp].z)));
            if (s0 == best) { bidx = 2 * jp; break; }
            float s1 = fmaf(sP[jp].y, c.x, fmaf(sP[jp].w, c.y, fmaf(sQ[jp].y, c.z, sQ[jp].w)));
            if (s1 == best) { bidx = 2 * jp + 1; break; }
        }
        if (bidx >= 0) {
            int l = __float_as_int(c.w);
            ull pk = ((ull)f2u(-best) << 32) | (unsigned)(tstart + bidx);
            atomicMin(&g_fwd[l], pk);
        }
    }
}

// final L1 loss over kept candidates
__global__ void k_final(const float* __restrict__ crgb, const float* __restrict__ trgb,
                        float* out, int N) {
    int p = blockIdx.x * blockDim.x + threadIdx.x;
    float loss = 0.f;
    if (p < g_count) {
        int l = g_candIdx[p];
        float r0, r1, r2;
        if (g_exact[l]) {
            r0 = g_exrgb[3 * l]; r1 = g_exrgb[3 * l + 1]; r2 = g_exrgb[3 * l + 2];
        } else {
            float den = g_den[l];
            if (den != 0.f) {
                r0 = g_num[3 * l] / den;
                r1 = g_num[3 * l + 1] / den;
                r2 = g_num[3 * l + 2] / den;
            } else {
                ull pk = g_fwd[l];
                unsigned ti = (unsigned)(pk & 0xFFFFFFFFULL);
                if (ti < (unsigned)N) {
                    r0 = trgb[3 * ti]; r1 = trgb[3 * ti + 1]; r2 = trgb[3 * ti + 2];
                } else {
                    r0 = r1 = r2 = 0.f;
                }
            }
        }
        float q0 = crgb[3 * l] * 255.f;
        float q1 = crgb[3 * l + 1] * 255.f;
        float q2 = crgb[3 * l + 2] * 255.f;
        loss = fabsf(q0 - r0) + fabsf(q1 - r1) + fabsf(q2 - r2);
    }
    float s = blockReduceSum(loss);
    if (threadIdx.x == 0) atomicAdd(out + 1, s);
}

// ---------------- launch ----------------
extern "C" void kernel_launch(void* const* d_in, const int* in_sizes, int n_in,
                              void* d_out, int out_size) {
    const float* pred = (const float*)d_in[0];
    const float* cxyz = (const float*)d_in[1];
    const float* crgb = (const float*)d_in[2];
    const float* txyz = (const float*)d_in[3];
    const float* trgb = (const float*)d_in[4];
    const int*   kt   = (const int*)d_in[5];
    const int*   pn   = (const int*)d_in[6];
    float* out = (float*)d_out;

    int L = in_sizes[0];
    int N = in_sizes[3] / 3;
    int M = L > N ? L : N;

    k_initprep<<<(M + 255) / 256, 256>>>(pred, out, L, N);
    k_select<<<1, 256>>>(pn, L);
    k_keep<<<(L + 255) / 256, 256>>>(pred, kt, cxyz, L, out);
    dim3 gb((L + TCB - 1) / TCB, (N + 511) / 512);
    k_bwd<<<gb, 256>>>(txyz, N);
    k_scatter<<<(N + 255) / 256, 256>>>(txyz, trgb, N);
    k_compactE<<<(L + 255) / 256, 256>>>(L);
    dim3 gf((L + 255) / 256, (N + TTF - 1) / TTF);
    k_fwd<<<gf, 256>>>(txyz, N);
    k_final<<<(L + 255) / 256, 256>>>(crgb, trgb, out, N);
}

// round 5
// speedup vs baseline: 1.4409x; 1.0716x over previous
#include <cuda_runtime.h>

#define LMAX 32768
#define NMAX 32768
#define TCB 256    // backward: candidates per smem tile (pairwise-packed, 4KB)
#define TTF 256    // forward: targets per smem tile (pairwise-packed, 4KB)
#define CHKP 16    // chunk in PAIRS (32 items) for index rescan

#define POSINF __int_as_float(0x7F800000)
#define NEGINF __int_as_float(0xFF800000)

typedef unsigned long long ull;

// ---------------- device scratch (no allocations allowed) ----------------
__device__ unsigned int  g_keys[LMAX];
__device__ unsigned char g_islm[LMAX];
__device__ float         g_thr;
__device__ int           g_count;
__device__ int           g_ecount;
__device__ float4        g_candC[LMAX];     // kept cand: x,y,z, mh=-0.5*|c|^2
__device__ int           g_candIdx[LMAX];   // compacted kept -> original index
__device__ ull           g_bwd[NMAX];       // per target: (sortable(-smax)<<32)|candOrigIdx
__device__ ull           g_fwd[LMAX];       // per cand:   (sortable(-smax)<<32)|tgtIdx
__device__ float         g_num[LMAX * 3];
__device__ float         g_den[LMAX];
__device__ int           g_exact[LMAX];
__device__ float         g_exrgb[LMAX * 3];
__device__ float4        g_eC[LMAX];        // compacted empty cands: x,y,z, bits(origIdx)

// ---------------- helpers ----------------
__device__ __forceinline__ unsigned f2u(float f) {
    unsigned i = __float_as_uint(f);
    return (i & 0x80000000u) ? ~i : (i | 0x80000000u);
}
__device__ __forceinline__ float u2f(unsigned u) {
    unsigned i = (u & 0x80000000u) ? (u & 0x7FFFFFFFu) : ~u;
    return __uint_as_float(i);
}
__device__ __forceinline__ ull fma2(ull a, ull b, ull c) {
    ull d;
    asm("fma.rn.f32x2 %0, %1, %2, %3;" : "=l"(d) : "l"(a), "l"(b), "l"(c));
    return d;
}
__device__ __forceinline__ ull pk2(float lo, float hi) {
    ull r;
    asm("mov.b64 %0, {%1, %2};" : "=l"(r) : "f"(lo), "f"(hi));
    return r;
}
__device__ __forceinline__ void up2(ull v, float& lo, float& hi) {
    asm("mov.b64 {%0, %1}, %2;" : "=f"(lo), "=f"(hi) : "l"(v));
}

__device__ __forceinline__ float blockReduceSum(float v) {
    __shared__ float sh[32];
    int lane = threadIdx.x & 31, w = threadIdx.x >> 5;
#pragma unroll
    for (int o = 16; o > 0; o >>= 1) v += __shfl_down_sync(0xFFFFFFFFu, v, o);
    if (lane == 0) sh[w] = v;
    __syncthreads();
    v = (threadIdx.x < (blockDim.x >> 5)) ? sh[lane] : 0.f;
    if (w == 0) {
#pragma unroll
        for (int o = 16; o > 0; o >>= 1) v += __shfl_down_sync(0xFFFFFFFFu, v, o);
    }
    return v;
}

// ---------------- kernels ----------------
// init of all scratch + local-max over groups of 8 + sortable keys (fused)
__global__ void k_initprep(const float* __restrict__ pred, float* out, int L, int N) {
    int i = blockIdx.x * blockDim.x + threadIdx.x;
    if (i == 0) { g_count = 0; g_ecount = 0; out[0] = 0.f; out[1] = 0.f; }
    if (i < L) {
        g_num[3 * i] = 0.f; g_num[3 * i + 1] = 0.f; g_num[3 * i + 2] = 0.f;
        g_den[i] = 0.f; g_exact[i] = 0;
        g_fwd[i] = 0xFFFFFFFFFFFFFFFFULL;
    }
    if (i < N) g_bwd[i] = 0xFFFFFFFFFFFFFFFFULL;
    int G = L >> 3;
    if (i < G) {
        const float* p = pred + i * 8;
        float bv = p[0]; int bi = 0;
#pragma unroll
        for (int j = 1; j < 8; j++) { float v = p[j]; if (v > bv) { bv = v; bi = j; } }
#pragma unroll
        for (int j = 0; j < 8; j++) {
            bool lm = (j == bi);
            g_islm[i * 8 + j] = lm ? 1 : 0;
            g_keys[i * 8 + j] = f2u(lm ? POSINF : p[j]);
        }
    }
}

// single-block MSD radix select: threshold = k-th smallest of keys, k = L - points_num
__global__ void k_select(const int* __restrict__ pn, int L) {
    __shared__ unsigned hist[256];
    __shared__ unsigned s_prefix;
    __shared__ int s_rank;
    int tid = threadIdx.x;
    if (tid == 0) { s_prefix = 0u; s_rank = L - pn[0]; }
    __syncthreads();
    for (int round = 0; round < 4; round++) {
        int shift = 24 - 8 * round;
        hist[tid] = 0u;
        __syncthreads();
        unsigned pref = s_prefix;
        unsigned mask = (round == 0) ? 0u : (0xFFFFFFFFu << (shift + 8));
        for (int i = tid; i < L; i += 256) {
            unsigned u = g_keys[i];
            if ((u & mask) == pref) atomicAdd(&hist[(u >> shift) & 0xFFu], 1u);
        }
        __syncthreads();
        if (tid == 0) {
            int r = s_rank; unsigned b = 0;
            while (b < 256u) { int c = (int)hist[b]; if (c >= r) break; r -= c; b++; }
            s_rank = r;
            s_prefix = pref | (b << shift);
        }
        __syncthreads();
    }
    if (tid == 0) g_thr = u2f(s_prefix);
}

// keep mask, BCE (coord loss), warp-aggregated compaction
__global__ void k_keep(const float* __restrict__ pred, const int* __restrict__ kt,
                       const float* __restrict__ cxyz, int L, float* out) {
    int i = blockIdx.x * blockDim.x + threadIdx.x;
    float bce = 0.f; bool keep = false;
    float thr = g_thr;
    if (i < L) {
        float p = pred[i];
        float t = (float)kt[i];
        bce = fmaxf(p, 0.f) - p * t + log1pf(expf(-fabsf(p)));
        keep = (p > thr) || (g_islm[i] != 0);
    }
    unsigned m = __ballot_sync(0xFFFFFFFFu, keep);
    if (keep) {
        int lane = threadIdx.x & 31;
        int leader = __ffs(m) - 1;
        int base = 0;
        if (lane == leader) base = atomicAdd(&g_count, __popc(m));
        base = __shfl_sync(m, base, leader);
        int pos = base + __popc(m & ((1u << lane) - 1u));
        float x = cxyz[3 * i], y = cxyz[3 * i + 1], z = cxyz[3 * i + 2];
        float mh = -0.5f * fmaf(z, z, fmaf(y, y, x * x));
        g_candC[pos] = make_float4(x, y, z, mh);
        g_candIdx[pos] = i;
    }
    float s = blockReduceSum(bce);
    if (threadIdx.x == 0) atomicAdd(out, s);
}

// backward sweep: per target, argmax of s = dot(t,c) - 0.5|c|^2 over kept candidates.
// Candidates pairwise-packed into f32x2 lanes; 1 target/thread; small tiles for occupancy.
// smem: sP[jp]=(x_even,x_odd,y_even,y_odd), sQ[jp]=(z_even,z_odd,mh_even,mh_odd)
__global__ void __launch_bounds__(256, 6) k_bwd(const float* __restrict__ txyz, int N) {
    __shared__ float4 sP[TCB / 2], sQ[TCB / 2];
    int count = g_count;
    int tstart = blockIdx.x * TCB;
    if (tstart >= count) return;
    int tid = threadIdx.x;
    {
        int p = tstart + tid;
        float4 c = (p < count) ? g_candC[p] : make_float4(0.f, 0.f, 0.f, NEGINF);
        int jp = tid >> 1;
        if ((tid & 1) == 0) { sP[jp].x = c.x; sP[jp].z = c.y; sQ[jp].x = c.z; sQ[jp].z = c.w; }
        else                { sP[jp].y = c.x; sP[jp].w = c.y; sQ[jp].y = c.z; sQ[jp].w = c.w; }
    }
    __syncthreads();

    int t = blockIdx.y * 256 + tid;
    bool v = t < N;
    float x = v ? txyz[3 * t] : 0.f;
    float y = v ? txyz[3 * t + 1] : 0.f;
    float z = v ? txyz[3 * t + 2] : 0.f;
    ull tx = pk2(x, x), ty = pk2(y, y), tz = pk2(z, z);

    float best = NEGINF; int kc = 0;
    for (int cs = 0; cs < TCB / 2; cs += CHKP) {
        float a0 = NEGINF, a1 = NEGINF;
#pragma unroll
        for (int jp = cs; jp < cs + CHKP; jp++) {
            ulonglong2 qp = *reinterpret_cast<const ulonglong2*>(&sP[jp]);
            ulonglong2 qq = *reinterpret_cast<const ulonglong2*>(&sQ[jp]);
            ull s = fma2(qp.x, tx, fma2(qp.y, ty, fma2(qq.x, tz, qq.y)));
            float lo, hi;
            up2(s, lo, hi);
            a0 = fmaxf(a0, lo); a1 = fmaxf(a1, hi);
        }
        float m = fmaxf(a0, a1);
        if (m > best) { best = m; kc = cs; }
    }

    if (v) {
        int bidx = -1;
        for (int jp = kc; jp < kc + CHKP; jp++) {
            float s0 = fmaf(sP[jp].x, x, fmaf(sP[jp].z, y, fmaf(sQ[jp].x, z, sQ[jp].z)));
            if (s0 == best) { bidx = 2 * jp; break; }
            float s1 = fmaf(sP[jp].y, x, fmaf(sP[jp].w, y, fmaf(sQ[jp].y, z, sQ[jp].w)));
            if (s1 == best) { bidx = 2 * jp + 1; break; }
        }
        if (bidx >= 0) {
            ull pk = ((ull)f2u(-best) << 32) | (unsigned)g_candIdx[tstart + bidx];
            atomicMin(&g_bwd[t], pk);
        }
    }
}

// per target: scatter weighted rgb into the winning candidate
__global__ void k_scatter(const float* __restrict__ txyz, const float* __restrict__ trgb, int N) {
    int n = blockIdx.x * blockDim.x + threadIdx.x;
    if (n >= N) return;
    ull pk = g_bwd[n];
    if (pk == 0xFFFFFFFFFFFFFFFFULL) return;
    unsigned u = (unsigned)(pk >> 32);
    int idx = (int)(unsigned)(pk & 0xFFFFFFFFULL);
    float m = u2f(u);  // m = h - dot, d2 = t2 + 2m
    float tx = txyz[3 * n], ty = txyz[3 * n + 1], tz = txyz[3 * n + 2];
    float t2 = fmaf(tz, tz, fmaf(ty, ty, tx * tx));
    float d2 = fmaxf(fmaf(2.f, m, t2), 0.f);
    float r = trgb[3 * n], g = trgb[3 * n + 1], b = trgb[3 * n + 2];
    if (d2 == 0.f) {
        g_exact[idx] = 1;
        g_exrgb[3 * idx] = r; g_exrgb[3 * idx + 1] = g; g_exrgb[3 * idx + 2] = b;
    } else {
        float w = 1.0f / sqrtf(fmaxf(d2, 1e-30f));
        atomicAdd(&g_num[3 * idx],     r * w);
        atomicAdd(&g_num[3 * idx + 1], g * w);
        atomicAdd(&g_num[3 * idx + 2], b * w);
        atomicAdd(&g_den[idx], w);
    }
}

// compact kept candidates that received no color (the "empty" set)
__global__ void k_compactE(int L) {
    int p = blockIdx.x * blockDim.x + threadIdx.x;
    bool e = false; int l = 0;
    float x = 0.f, y = 0.f, z = 0.f;
    if (p < g_count) {
        l = g_candIdx[p];
        if (g_den[l] == 0.f && g_exact[l] == 0) {
            e = true;
            float4 c = g_candC[p];
            x = c.x; y = c.y; z = c.z;
        }
    }
    unsigned m = __ballot_sync(0xFFFFFFFFu, e);
    if (e) {
        int lane = threadIdx.x & 31;
        int leader = __ffs(m) - 1;
        int base = 0;
        if (lane == leader) base = atomicAdd(&g_ecount, __popc(m));
        base = __shfl_sync(m, base, leader);
        int pos = base + __popc(m & ((1u << lane) - 1u));
        g_eC[pos] = make_float4(x, y, z, __int_as_float(l));
    }
}

// forward sweep: per empty candidate, argmax of s = dot(c,t) - 0.5|t|^2 over all targets.
// Targets pairwise-packed into f32x2 lanes; 1 empty cand/thread; small tiles.
__global__ void __launch_bounds__(256, 6) k_fwd(const float* __restrict__ txyz, int N) {
    int ec = g_ecount;
    int estart = blockIdx.x * 256;
    if (estart >= ec) return;
    __shared__ float4 sP[TTF / 2], sQ[TTF / 2];
    int tid = threadIdx.x;
    int tstart = blockIdx.y * TTF;
    {
        int t = tstart + tid;
        float x = 0.f, y = 0.f, z = 0.f, mh = NEGINF;
        if (t < N) {
            x = txyz[3 * t]; y = txyz[3 * t + 1]; z = txyz[3 * t + 2];
            mh = -0.5f * fmaf(z, z, fmaf(y, y, x * x));
        }
        int jp = tid >> 1;
        if ((tid & 1) == 0) { sP[jp].x = x; sP[jp].z = y; sQ[jp].x = z; sQ[jp].z = mh; }
        else                { sP[jp].y = x; sP[jp].w = y; sQ[jp].y = z; sQ[jp].w = mh; }
    }
    __syncthreads();

    int e = estart + tid;
    bool v = e < ec;
    float4 c = v ? g_eC[e] : make_float4(0.f, 0.f, 0.f, 0.f);
    ull cx = pk2(c.x, c.x), cy = pk2(c.y, c.y), cz = pk2(c.z, c.z);

    float best = NEGINF; int kc = 0;
    for (int cs = 0; cs < TTF / 2; cs += CHKP) {
        float a0 = NEGINF, a1 = NEGINF;
#pragma unroll
        for (int jp = cs; jp < cs + CHKP; jp++) {
            ulonglong2 qp = *reinterpret_cast<const ulonglong2*>(&sP[jp]);
            ulonglong2 qq = *reinterpret_cast<const ulonglong2*>(&sQ[jp]);
            ull s = fma2(qp.x, cx, fma2(qp.y, cy, fma2(qq.x, cz, qq.y)));
            float lo, hi;
            up2(s, lo, hi);
            a0 = fmaxf(a0, lo); a1 = fmaxf(a1, hi);
        }
        float m = fmaxf(a0, a1);
        if (m > best) { best = m; kc = cs; }
    }

    if (v) {
        int bidx = -1;
        for (int jp = kc; jp < kc + CHKP; jp++) {
            float s0 = fmaf(sP[jp].x, c.x, fmaf(sP[jp].z, c.y, fmaf(sQ[jp].x, c.z, sQ[jp].z)));
            if (s0 == best) { bidx = 2 * jp; break; }
            float s1 = fmaf(sP[jp].y, c.x, fmaf(sP[jp].w, c.y, fmaf(sQ[jp].y, c.z, sQ[jp].w)));
            if (s1 == best) { bidx = 2 * jp + 1; break; }
        }
        if (bidx >= 0) {
            int l = __float_as_int(c.w);
            ull pk = ((ull)f2u(-best) << 32) | (unsigned)(tstart + bidx);
            atomicMin(&g_fwd[l], pk);
        }
    }
}

// final L1 loss over kept candidates
__global__ void k_final(const float* __restrict__ crgb, const float* __restrict__ trgb,
                        float* out, int N) {
    int p = blockIdx.x * blockDim.x + threadIdx.x;
    float loss = 0.f;
    if (p < g_count) {
        int l = g_candIdx[p];
        float r0, r1, r2;
        if (g_exact[l]) {
            r0 = g_exrgb[3 * l]; r1 = g_exrgb[3 * l + 1]; r2 = g_exrgb[3 * l + 2];
        } else {
            float den = g_den[l];
            if (den != 0.f) {
                r0 = g_num[3 * l] / den;
                r1 = g_num[3 * l + 1] / den;
                r2 = g_num[3 * l + 2] / den;
            } else {
                ull pk = g_fwd[l];
                unsigned ti = (unsigned)(pk & 0xFFFFFFFFULL);
                if (ti < (unsigned)N) {
                    r0 = trgb[3 * ti]; r1 = trgb[3 * ti + 1]; r2 = trgb[3 * ti + 2];
                } else {
                    r0 = r1 = r2 = 0.f;
                }
            }
        }
        float q0 = crgb[3 * l] * 255.f;
        float q1 = crgb[3 * l + 1] * 255.f;
        float q2 = crgb[3 * l + 2] * 255.f;
        loss = fabsf(q0 - r0) + fabsf(q1 - r1) + fabsf(q2 - r2);
    }
    float s = blockReduceSum(loss);
    if (threadIdx.x == 0) atomicAdd(out + 1, s);
}

// ---------------- launch ----------------
extern "C" void kernel_launch(void* const* d_in, const int* in_sizes, int n_in,
                              void* d_out, int out_size) {
    const float* pred = (const float*)d_in[0];
    const float* cxyz = (const float*)d_in[1];
    const float* crgb = (const float*)d_in[2];
    const float* txyz = (const float*)d_in[3];
    const float* trgb = (const float*)d_in[4];
    const int*   kt   = (const int*)d_in[5];
    const int*   pn   = (const int*)d_in[6];
    float* out = (float*)d_out;

    int L = in_sizes[0];
    int N = in_sizes[3] / 3;
    int M = L > N ? L : N;

    k_initprep<<<(M + 255) / 256, 256>>>(pred, out, L, N);
    k_select<<<1, 256>>>(pn, L);
    k_keep<<<(L + 255) / 256, 256>>>(pred, kt, cxyz, L, out);
    dim3 gb((L + TCB - 1) / TCB, (N + 255) / 256);
    k_bwd<<<gb, 256>>>(txyz, N);
    k_scatter<<<(N + 255) / 256, 256>>>(txyz, trgb, N);
    k_compactE<<<(L + 255) / 256, 256>>>(L);
    dim3 gf((L + 255) / 256, (N + TTF - 1) / 256);
    k_fwd<<<gf, 256>>>(txyz, N);
    k_final<<<(L + 255) / 256, 256>>>(crgb, trgb, out, N);
}

// round 6
// speedup vs baseline: 1.5045x; 1.0442x over previous
#include <cuda_runtime.h>

#define LMAX 32768
#define NMAX 32768
#define TCB 128    // backward: candidates per smem tile (pairwise-packed, 2KB)
#define TTF 128    // forward: targets per smem tile (pairwise-packed, 2KB)
#define CHKP 16    // chunk in PAIRS (32 items) for index rescan

#define POSINF __int_as_float(0x7F800000)
#define NEGINF __int_as_float(0xFF800000)

typedef unsigned long long ull;

// ---------------- device scratch (no allocations allowed) ----------------
__device__ unsigned int  g_keys[LMAX];
__device__ unsigned char g_islm[LMAX];
__device__ float         g_thr;
__device__ int           g_count;
__device__ int           g_ecount;
__device__ float4        g_candC[LMAX];     // kept cand: x,y,z, mh=-0.5*|c|^2
__device__ int           g_candIdx[LMAX];   // compacted kept -> original index
__device__ ull           g_bwd[NMAX];       // per target: (sortable(-smax)<<32)|candOrigIdx
__device__ ull           g_fwd[LMAX];       // per cand:   (sortable(-smax)<<32)|tgtIdx
__device__ float         g_num[LMAX * 3];
__device__ float         g_den[LMAX];
__device__ int           g_exact[LMAX];
__device__ float         g_exrgb[LMAX * 3];
__device__ float4        g_eC[LMAX];        // compacted empty cands: x,y,z, bits(origIdx)

// ---------------- helpers ----------------
__device__ __forceinline__ unsigned f2u(float f) {
    unsigned i = __float_as_uint(f);
    return (i & 0x80000000u) ? ~i : (i | 0x80000000u);
}
__device__ __forceinline__ float u2f(unsigned u) {
    unsigned i = (u & 0x80000000u) ? (u & 0x7FFFFFFFu) : ~u;
    return __uint_as_float(i);
}
__device__ __forceinline__ ull fma2(ull a, ull b, ull c) {
    ull d;
    asm("fma.rn.f32x2 %0, %1, %2, %3;" : "=l"(d) : "l"(a), "l"(b), "l"(c));
    return d;
}
__device__ __forceinline__ ull pk2(float lo, float hi) {
    ull r;
    asm("mov.b64 %0, {%1, %2};" : "=l"(r) : "f"(lo), "f"(hi));
    return r;
}
__device__ __forceinline__ void up2(ull v, float& lo, float& hi) {
    asm("mov.b64 {%0, %1}, %2;" : "=f"(lo), "=f"(hi) : "l"(v));
}

__device__ __forceinline__ float blockReduceSum(float v) {
    __shared__ float sh[32];
    int lane = threadIdx.x & 31, w = threadIdx.x >> 5;
#pragma unroll
    for (int o = 16; o > 0; o >>= 1) v += __shfl_down_sync(0xFFFFFFFFu, v, o);
    if (lane == 0) sh[w] = v;
    __syncthreads();
    v = (threadIdx.x < (blockDim.x >> 5)) ? sh[lane] : 0.f;
    if (w == 0) {
#pragma unroll
        for (int o = 16; o > 0; o >>= 1) v += __shfl_down_sync(0xFFFFFFFFu, v, o);
    }
    return v;
}

// ---------------- kernels ----------------
// init of all scratch + local-max over groups of 8 + sortable keys (fused)
__global__ void k_initprep(const float* __restrict__ pred, float* out, int L, int N) {
    int i = blockIdx.x * blockDim.x + threadIdx.x;
    if (i == 0) { g_count = 0; g_ecount = 0; out[0] = 0.f; out[1] = 0.f; }
    if (i < L) {
        g_num[3 * i] = 0.f; g_num[3 * i + 1] = 0.f; g_num[3 * i + 2] = 0.f;
        g_den[i] = 0.f; g_exact[i] = 0;
        g_fwd[i] = 0xFFFFFFFFFFFFFFFFULL;
    }
    if (i < N) g_bwd[i] = 0xFFFFFFFFFFFFFFFFULL;
    int G = L >> 3;
    if (i < G) {
        const float* p = pred + i * 8;
        float bv = p[0]; int bi = 0;
#pragma unroll
        for (int j = 1; j < 8; j++) { float v = p[j]; if (v > bv) { bv = v; bi = j; } }
#pragma unroll
        for (int j = 0; j < 8; j++) {
            bool lm = (j == bi);
            g_islm[i * 8 + j] = lm ? 1 : 0;
            g_keys[i * 8 + j] = f2u(lm ? POSINF : p[j]);
        }
    }
}

// single-block MSD radix select: threshold = k-th smallest of keys, k = L - points_num
__global__ void k_select(const int* __restrict__ pn, int L) {
    __shared__ unsigned hist[256];
    __shared__ unsigned s_prefix;
    __shared__ int s_rank;
    int tid = threadIdx.x;
    if (tid == 0) { s_prefix = 0u; s_rank = L - pn[0]; }
    __syncthreads();
    for (int round = 0; round < 4; round++) {
        int shift = 24 - 8 * round;
        if (tid < 256) hist[tid] = 0u;
        __syncthreads();
        unsigned pref = s_prefix;
        unsigned mask = (round == 0) ? 0u : (0xFFFFFFFFu << (shift + 8));
        for (int i = tid; i < L; i += blockDim.x) {
            unsigned u = g_keys[i];
            if ((u & mask) == pref) atomicAdd(&hist[(u >> shift) & 0xFFu], 1u);
        }
        __syncthreads();
        if (tid == 0) {
            int r = s_rank; unsigned b = 0;
            while (b < 256u) { int c = (int)hist[b]; if (c >= r) break; r -= c; b++; }
            s_rank = r;
            s_prefix = pref | (b << shift);
        }
        __syncthreads();
    }
    if (tid == 0) g_thr = u2f(s_prefix);
}

// keep mask, BCE (coord loss), warp-aggregated compaction
__global__ void k_keep(const float* __restrict__ pred, const int* __restrict__ kt,
                       const float* __restrict__ cxyz, int L, float* out) {
    int i = blockIdx.x * blockDim.x + threadIdx.x;
    float bce = 0.f; bool keep = false;
    float thr = g_thr;
    if (i < L) {
        float p = pred[i];
        float t = (float)kt[i];
        bce = fmaxf(p, 0.f) - p * t + log1pf(expf(-fabsf(p)));
        keep = (p > thr) || (g_islm[i] != 0);
    }
    unsigned m = __ballot_sync(0xFFFFFFFFu, keep);
    if (keep) {
        int lane = threadIdx.x & 31;
        int leader = __ffs(m) - 1;
        int base = 0;
        if (lane == leader) base = atomicAdd(&g_count, __popc(m));
        base = __shfl_sync(m, base, leader);
        int pos = base + __popc(m & ((1u << lane) - 1u));
        float x = cxyz[3 * i], y = cxyz[3 * i + 1], z = cxyz[3 * i + 2];
        float mh = -0.5f * fmaf(z, z, fmaf(y, y, x * x));
        g_candC[pos] = make_float4(x, y, z, mh);
        g_candIdx[pos] = i;
    }
    float s = blockReduceSum(bce);
    if (threadIdx.x == 0) atomicAdd(out, s);
}

// backward sweep: per target, argmax of s = dot(t,c) - 0.5|c|^2 over kept candidates.
// Candidates pairwise-packed into f32x2 lanes in smem; 4 targets/thread (register-blocked)
// so each LDS.128 feeds 12 fma2. Chunk max + exact scalar rescan for the index.
__global__ void __launch_bounds__(128) k_bwd(const float* __restrict__ txyz, int N) {
    __shared__ float4 sP[TCB / 2], sQ[TCB / 2];
    int count = g_count;
    int tstart = blockIdx.x * TCB;
    if (tstart >= count) return;
    int tid = threadIdx.x;
    {
        int p = tstart + tid;
        float4 c = (p < count) ? g_candC[p] : make_float4(0.f, 0.f, 0.f, NEGINF);
        int jp = tid >> 1;
        if ((tid & 1) == 0) { sP[jp].x = c.x; sP[jp].z = c.y; sQ[jp].x = c.z; sQ[jp].z = c.w; }
        else                { sP[jp].y = c.x; sP[jp].w = c.y; sQ[jp].y = c.z; sQ[jp].w = c.w; }
    }
    __syncthreads();

    int tbase = blockIdx.y * 512 + tid;
    float X[4], Y[4], Z[4];
    ull TX[4], TY[4], TZ[4];
    bool V[4];
#pragma unroll
    for (int q = 0; q < 4; q++) {
        int t = tbase + 128 * q;
        V[q] = t < N;
        X[q] = V[q] ? txyz[3 * t] : 0.f;
        Y[q] = V[q] ? txyz[3 * t + 1] : 0.f;
        Z[q] = V[q] ? txyz[3 * t + 2] : 0.f;
        TX[q] = pk2(X[q], X[q]); TY[q] = pk2(Y[q], Y[q]); TZ[q] = pk2(Z[q], Z[q]);
    }

    float best[4] = {NEGINF, NEGINF, NEGINF, NEGINF};
    int kc[4] = {0, 0, 0, 0};
    for (int cs = 0; cs < TCB / 2; cs += CHKP) {
        float a0[4] = {NEGINF, NEGINF, NEGINF, NEGINF};
        float a1[4] = {NEGINF, NEGINF, NEGINF, NEGINF};
#pragma unroll 4
        for (int jp = cs; jp < cs + CHKP; jp++) {
            ulonglong2 qp = *reinterpret_cast<const ulonglong2*>(&sP[jp]);
            ulonglong2 qq = *reinterpret_cast<const ulonglong2*>(&sQ[jp]);
#pragma unroll
            for (int q = 0; q < 4; q++) {
                ull s = fma2(qp.x, TX[q], fma2(qp.y, TY[q], fma2(qq.x, TZ[q], qq.y)));
                float lo, hi;
                up2(s, lo, hi);
                a0[q] = fmaxf(a0[q], lo); a1[q] = fmaxf(a1[q], hi);
            }
        }
#pragma unroll
        for (int q = 0; q < 4; q++) {
            float m = fmaxf(a0[q], a1[q]);
            if (m > best[q]) { best[q] = m; kc[q] = cs; }
        }
    }

#pragma unroll
    for (int q = 0; q < 4; q++) {
        if (!V[q]) continue;
        int bidx = -1;
        for (int jp = kc[q]; jp < kc[q] + CHKP; jp++) {
            float s0 = fmaf(sP[jp].x, X[q], fmaf(sP[jp].z, Y[q], fmaf(sQ[jp].x, Z[q], sQ[jp].z)));
            if (s0 == best[q]) { bidx = 2 * jp; break; }
            float s1 = fmaf(sP[jp].y, X[q], fmaf(sP[jp].w, Y[q], fmaf(sQ[jp].y, Z[q], sQ[jp].w)));
            if (s1 == best[q]) { bidx = 2 * jp + 1; break; }
        }
        if (bidx >= 0) {
            ull pk = ((ull)f2u(-best[q]) << 32) | (unsigned)g_candIdx[tstart + bidx];
            atomicMin(&g_bwd[tbase + 128 * q], pk);
        }
    }
}

// per target: scatter weighted rgb into the winning candidate
__global__ void k_scatter(const float* __restrict__ txyz, const float* __restrict__ trgb, int N) {
    int n = blockIdx.x * blockDim.x + threadIdx.x;
    if (n >= N) return;
    ull pk = g_bwd[n];
    if (pk == 0xFFFFFFFFFFFFFFFFULL) return;
    unsigned u = (unsigned)(pk >> 32);
    int idx = (int)(unsigned)(pk & 0xFFFFFFFFULL);
    float m = u2f(u);  // m = h - dot, d2 = t2 + 2m
    float tx = txyz[3 * n], ty = txyz[3 * n + 1], tz = txyz[3 * n + 2];
    float t2 = fmaf(tz, tz, fmaf(ty, ty, tx * tx));
    float d2 = fmaxf(fmaf(2.f, m, t2), 0.f);
    float r = trgb[3 * n], g = trgb[3 * n + 1], b = trgb[3 * n + 2];
    if (d2 == 0.f) {
        g_exact[idx] = 1;
        g_exrgb[3 * idx] = r; g_exrgb[3 * idx + 1] = g; g_exrgb[3 * idx + 2] = b;
    } else {
        float w = 1.0f / sqrtf(fmaxf(d2, 1e-30f));
        atomicAdd(&g_num[3 * idx],     r * w);
        atomicAdd(&g_num[3 * idx + 1], g * w);
        atomicAdd(&g_num[3 * idx + 2], b * w);
        atomicAdd(&g_den[idx], w);
    }
}

// compact kept candidates that received no color (the "empty" set)
__global__ void k_compactE(int L) {
    int p = blockIdx.x * blockDim.x + threadIdx.x;
    bool e = false; int l = 0;
    float x = 0.f, y = 0.f, z = 0.f;
    if (p < g_count) {
        l = g_candIdx[p];
        if (g_den[l] == 0.f && g_exact[l] == 0) {
            e = true;
            float4 c = g_candC[p];
            x = c.x; y = c.y; z = c.z;
        }
    }
    unsigned m = __ballot_sync(0xFFFFFFFFu, e);
    if (e) {
        int lane = threadIdx.x & 31;
        int leader = __ffs(m) - 1;
        int base = 0;
        if (lane == leader) base = atomicAdd(&g_ecount, __popc(m));
        base = __shfl_sync(m, base, leader);
        int pos = base + __popc(m & ((1u << lane) - 1u));
        g_eC[pos] = make_float4(x, y, z, __int_as_float(l));
    }
}

// forward sweep: per empty candidate, argmax of s = dot(c,t) - 0.5|t|^2 over all targets.
// Targets pairwise-packed in smem; 2 empty cands/thread (register-blocked).
__global__ void __launch_bounds__(128) k_fwd(const float* __restrict__ txyz, int N) {
    int ec = g_ecount;
    int estart = blockIdx.x * 256;
    if (estart >= ec) return;
    __shared__ float4 sP[TTF / 2], sQ[TTF / 2];
    int tid = threadIdx.x;
    int tstart = blockIdx.y * TTF;
    {
        int t = tstart + tid;
        float x = 0.f, y = 0.f, z = 0.f, mh = NEGINF;
        if (t < N) {
            x = txyz[3 * t]; y = txyz[3 * t + 1]; z = txyz[3 * t + 2];
            mh = -0.5f * fmaf(z, z, fmaf(y, y, x * x));
        }
        int jp = tid >> 1;
        if ((tid & 1) == 0) { sP[jp].x = x; sP[jp].z = y; sQ[jp].x = z; sQ[jp].z = mh; }
        else                { sP[jp].y = x; sP[jp].w = y; sQ[jp].y = z; sQ[jp].w = mh; }
    }
    __syncthreads();

    int e0 = estart + tid, e1 = e0 + 128;
    bool v0 = e0 < ec, v1 = e1 < ec;
    float4 c0 = v0 ? g_eC[e0] : make_float4(0.f, 0.f, 0.f, 0.f);
    float4 c1 = v1 ? g_eC[e1] : make_float4(0.f, 0.f, 0.f, 0.f);
    ull cx0 = pk2(c0.x, c0.x), cy0 = pk2(c0.y, c0.y), cz0 = pk2(c0.z, c0.z);
    ull cx1 = pk2(c1.x, c1.x), cy1 = pk2(c1.y, c1.y), cz1 = pk2(c1.z, c1.z);

    float best0 = NEGINF, best1 = NEGINF;
    int kc0 = 0, kc1 = 0;
    for (int cs = 0; cs < TTF / 2; cs += CHKP) {
        float a0 = NEGINF, a1 = NEGINF, b0 = NEGINF, b1 = NEGINF;
#pragma unroll 4
        for (int jp = cs; jp < cs + CHKP; jp++) {
            ulonglong2 qp = *reinterpret_cast<const ulonglong2*>(&sP[jp]);
            ulonglong2 qq = *reinterpret_cast<const ulonglong2*>(&sQ[jp]);
            ull s0 = fma2(qp.x, cx0, fma2(qp.y, cy0, fma2(qq.x, cz0, qq.y)));
            ull s1 = fma2(qp.x, cx1, fma2(qp.y, cy1, fma2(qq.x, cz1, qq.y)));
            float l0, h0, l1, h1;
            up2(s0, l0, h0); up2(s1, l1, h1);
            a0 = fmaxf(a0, l0); a1 = fmaxf(a1, h0);
            b0 = fmaxf(b0, l1); b1 = fmaxf(b1, h1);
        }
        float m0 = fmaxf(a0, a1), m1 = fmaxf(b0, b1);
        if (m0 > best0) { best0 = m0; kc0 = cs; }
        if (m1 > best1) { best1 = m1; kc1 = cs; }
    }

#define FWD_RESCAN(V, C, BV, KC)                                                            \
    if (V) {                                                                                \
        int bidx = -1;                                                                      \
        for (int jp = KC; jp < KC + CHKP; jp++) {                                           \
            float s0 = fmaf(sP[jp].x, (C).x, fmaf(sP[jp].z, (C).y, fmaf(sQ[jp].x, (C).z, sQ[jp].z))); \
            if (s0 == BV) { bidx = 2 * jp; break; }                                         \
            float s1 = fmaf(sP[jp].y, (C).x, fmaf(sP[jp].w, (C).y, fmaf(sQ[jp].y, (C).z, sQ[jp].w))); \
            if (s1 == BV) { bidx = 2 * jp + 1; break; }                                     \
        }                                                                                   \
        if (bidx >= 0) {                                                                    \
            int l = __float_as_int((C).w);                                                  \
            ull pk = ((ull)f2u(-(BV)) << 32) | (unsigned)(tstart + bidx);                   \
            atomicMin(&g_fwd[l], pk);                                                       \
        }                                                                                   \
    }
    FWD_RESCAN(v0, c0, best0, kc0)
    FWD_RESCAN(v1, c1, best1, kc1)
#undef FWD_RESCAN
}

// final L1 loss over kept candidates
__global__ void k_final(const float* __restrict__ crgb, const float* __restrict__ trgb,
                        float* out, int N) {
    int p = blockIdx.x * blockDim.x + threadIdx.x;
    float loss = 0.f;
    if (p < g_count) {
        int l = g_candIdx[p];
        float r0, r1, r2;
        if (g_exact[l]) {
            r0 = g_exrgb[3 * l]; r1 = g_exrgb[3 * l + 1]; r2 = g_exrgb[3 * l + 2];
        } else {
            float den = g_den[l];
            if (den != 0.f) {
                r0 = g_num[3 * l] / den;
                r1 = g_num[3 * l + 1] / den;
                r2 = g_num[3 * l + 2] / den;
            } else {
                ull pk = g_fwd[l];
                unsigned ti = (unsigned)(pk & 0xFFFFFFFFULL);
                if (ti < (unsigned)N) {
                    r0 = trgb[3 * ti]; r1 = trgb[3 * ti + 1]; r2 = trgb[3 * ti + 2];
                } else {
                    r0 = r1 = r2 = 0.f;
                }
            }
        }
        float q0 = crgb[3 * l] * 255.f;
        float q1 = crgb[3 * l + 1] * 255.f;
        float q2 = crgb[3 * l + 2] * 255.f;
        loss = fabsf(q0 - r0) + fabsf(q1 - r1) + fabsf(q2 - r2);
    }
    float s = blockReduceSum(loss);
    if (threadIdx.x == 0) atomicAdd(out + 1, s);
}

// ---------------- launch ----------------
extern "C" void kernel_launch(void* const* d_in, const int* in_sizes, int n_in,
                              void* d_out, int out_size) {
    const float* pred = (const float*)d_in[0];
    const float* cxyz = (const float*)d_in[1];
    const float* crgb = (const float*)d_in[2];
    const float* txyz = (const float*)d_in[3];
    const float* trgb = (const float*)d_in[4];
    const int*   kt   = (const int*)d_in[5];
    const int*   pn   = (const int*)d_in[6];
    float* out = (float*)d_out;

    int L = in_sizes[0];
    int N = in_sizes[3] / 3;
    int M = L > N ? L : N;

    k_initprep<<<(M + 255) / 256, 256>>>(pred, out, L, N);
    k_select<<<1, 1024>>>(pn, L);
    k_keep<<<(L + 255) / 256, 256>>>(pred, kt, cxyz, L, out);
    dim3 gb((L + TCB - 1) / TCB, (N + 511) / 512);
    k_bwd<<<gb, 128>>>(txyz, N);
    k_scatter<<<(N + 255) / 256, 256>>>(txyz, trgb, N);
    k_compactE<<<(L + 255) / 256, 256>>>(L);
    dim3 gf((L + 255) / 256, (N + TTF - 1) / TTF);
    k_fwd<<<gf, 128>>>(txyz, N);
    k_final<<<(L + 255) / 256, 256>>>(crgb, trgb, out, N);
}